// round 4
// baseline (speedup 1.0000x reference)
#include <cuda_runtime.h>

#define N_TOT 6016

// Static shape tables: sizes g = 256 + 16*g, g in [0,16)
__constant__ int c_node_start[17] = {
    0,256,528,816,1120,1440,1776,2128,2496,2880,3280,3696,4128,4576,5040,5520,6016};
__constant__ long long c_pair_start[17] = {
    0,65536,139520,222464,314880,417280,530176,654080,789504,936960,
    1096960,1270016,1456640,1657344,1872640,2103040,2349056};
__constant__ int c_tile_start[17] = {
    0,256,545,869,1230,1630,2071,2555,3084,3660,4285,4961,5690,6474,7315,8215,9176};

// staged per-node MLP output t[N_TOT][32]
__device__ float g_t[N_TOT * 32];

// ---------------------------------------------------------------------------
// Kernel 1: per-node MLP  t = relu(ape @ W1 + b1) @ W2 + b2
// 16 threads per node, two stages with smem hidden-exchange.
//   Stage A: thread p computes hidden h in [4p, 4p+4)   (64 FMA)
//   Stage B: thread p computes outputs c in {2p, 2p+1}  (128 FMA)
// 376 blocks x 16 nodes = 6016 nodes exactly.
// ---------------------------------------------------------------------------
__global__ __launch_bounds__(256)
void mlp_kernel(const float* __restrict__ ape,
                const float* __restrict__ W1, const float* __restrict__ b1,
                const float* __restrict__ W2, const float* __restrict__ b2) {
    __shared__ float sW1t[64 * 16];   // sW1t[h*16+k] = W1[k*64+h]
    __shared__ float sW2t[32 * 64];   // sW2t[c*64+h] = W2[h*32+c]
    __shared__ float sb1[64];
    __shared__ float sb2[32];
    __shared__ float s_h[16 * 64];    // hidden activations per node

    int tid = threadIdx.x;
    for (int idx = tid; idx < 64 * 16; idx += 256) {
        int h = idx >> 4, k = idx & 15;
        sW1t[idx] = W1[k * 64 + h];
    }
    for (int idx = tid; idx < 32 * 64; idx += 256) {
        int c = idx >> 6, h = idx & 63;
        sW2t[idx] = W2[h * 32 + c];
    }
    if (tid < 64) sb1[tid] = b1[tid];
    if (tid < 32) sb2[tid] = b2[tid];
    __syncthreads();

    int nl = tid >> 4;                 // node within block, 0..15
    int p  = tid & 15;
    int n  = blockIdx.x * 16 + nl;

    // load input row (broadcast across the 16 threads of this node)
    float a[16];
    const float4* ap = (const float4*)(ape + n * 16);
    float4 a0 = ap[0], a1 = ap[1], a2 = ap[2], a3 = ap[3];
    a[0]=a0.x; a[1]=a0.y; a[2]=a0.z; a[3]=a0.w;
    a[4]=a1.x; a[5]=a1.y; a[6]=a1.z; a[7]=a1.w;
    a[8]=a2.x; a[9]=a2.y; a[10]=a2.z; a[11]=a2.w;
    a[12]=a3.x; a[13]=a3.y; a[14]=a3.z; a[15]=a3.w;

    // Stage A: 4 hidden values
    float4 hv;
    {
        float r[4];
        const float4* w1v = (const float4*)(sW1t + (p * 4) * 16);
#pragma unroll
        for (int i = 0; i < 4; i++) {
            float4 w0 = w1v[i * 4 + 0], w1_ = w1v[i * 4 + 1];
            float4 w2_ = w1v[i * 4 + 2], w3 = w1v[i * 4 + 3];
            float v = sb1[p * 4 + i];
            v = fmaf(a[0],  w0.x, v);  v = fmaf(a[1],  w0.y, v);
            v = fmaf(a[2],  w0.z, v);  v = fmaf(a[3],  w0.w, v);
            v = fmaf(a[4],  w1_.x, v); v = fmaf(a[5],  w1_.y, v);
            v = fmaf(a[6],  w1_.z, v); v = fmaf(a[7],  w1_.w, v);
            v = fmaf(a[8],  w2_.x, v); v = fmaf(a[9],  w2_.y, v);
            v = fmaf(a[10], w2_.z, v); v = fmaf(a[11], w2_.w, v);
            v = fmaf(a[12], w3.x, v);  v = fmaf(a[13], w3.y, v);
            v = fmaf(a[14], w3.z, v);  v = fmaf(a[15], w3.w, v);
            r[i] = fmaxf(v, 0.0f);
        }
        hv.x = r[0]; hv.y = r[1]; hv.z = r[2]; hv.w = r[3];
    }
    ((float4*)s_h)[nl * 16 + p] = hv;
    __syncthreads();

    // Stage B: 2 outputs over all 64 hidden
    const float4* hvp = (const float4*)(s_h + nl * 64);
    float o0 = sb2[p * 2], o1 = sb2[p * 2 + 1];
    const float4* w2a = (const float4*)(sW2t + (p * 2) * 64);
    const float4* w2b = (const float4*)(sW2t + (p * 2 + 1) * 64);
#pragma unroll
    for (int q = 0; q < 16; q++) {
        float4 h4 = hvp[q];
        float4 ua = w2a[q];
        float4 ub = w2b[q];
        o0 = fmaf(h4.x, ua.x, o0); o0 = fmaf(h4.y, ua.y, o0);
        o0 = fmaf(h4.z, ua.z, o0); o0 = fmaf(h4.w, ua.w, o0);
        o1 = fmaf(h4.x, ub.x, o1); o1 = fmaf(h4.y, ub.y, o1);
        o1 = fmaf(h4.z, ub.z, o1); o1 = fmaf(h4.w, ub.w, o1);
    }
    float2 r2; r2.x = o0; r2.y = o1;
    *(float2*)(g_t + n * 32 + p * 2) = r2;
}

// ---------------------------------------------------------------------------
// Kernel 2: pair expansion. One block per 16x16 (i,j) tile of one graph.
// out[pair_start[b] + i*n_b + j][:] = t[start_b+i][:] + t[start_b+j][:]
// All n_b are multiples of 16 -> all tiles full, no bounds checks.
// ---------------------------------------------------------------------------
__global__ __launch_bounds__(256)
void pair_kernel(float* __restrict__ out) {
    int blk = blockIdx.x;

    // find graph b (uniform across block; 15 predicated compares)
    int b = 0;
#pragma unroll
    for (int g = 1; g < 16; g++)
        if (blk >= c_tile_start[g]) b = g;

    int lt  = blk - c_tile_start[b];
    int tpr = 16 + b;            // tiles per row = n_b/16
    int nb  = tpr << 4;          // n_b
    int ti  = lt / tpr;
    int tj  = lt - ti * tpr;
    int ns  = c_node_start[b];
    long long ps = c_pair_start[b];

    __shared__ float4 s_ti[16 * 8];   // 16 i-rows x 8 float4
    __shared__ float4 s_tj[16 * 8];   // 16 j-rows x 8 float4

    const float4* tp = (const float4*)g_t;
    int tid = threadIdx.x;
    if (tid < 128) {
        s_ti[tid] = tp[(ns + ti * 16) * 8 + tid];
    } else {
        s_tj[tid - 128] = tp[(ns + tj * 16) * 8 + (tid - 128)];
    }
    __syncthreads();

    float4* op = (float4*)out;
    int l    = tid & 127;        // position within a 16-row (j) group: j*8+q
    int half = tid >> 7;         // 0 or 1: which ii this thread covers per step
    int q    = l & 7;

    float4 vj = s_tj[l];         // t[j-row], float4 q — reused for all 8 steps

    long long rowbase = ps + (long long)(ti * 16) * nb + tj * 16;

#pragma unroll
    for (int step = 0; step < 8; step++) {
        int ii = step * 2 + half;
        float4 vi = s_ti[ii * 8 + q];
        float4 v;
        v.x = vi.x + vj.x; v.y = vi.y + vj.y;
        v.z = vi.z + vj.z; v.w = vi.w + vj.w;
        // 128 threads write 128 consecutive float4 (2KB contiguous)
        op[(rowbase + (long long)ii * nb) * 8 + l] = v;
    }
}

// ---------------------------------------------------------------------------
extern "C" void kernel_launch(void* const* d_in, const int* in_sizes, int n_in,
                              void* d_out, int out_size) {
    const float* ape = (const float*)d_in[0];
    const float* W1  = (const float*)d_in[1];
    const float* b1  = (const float*)d_in[2];
    const float* W2  = (const float*)d_in[3];
    const float* b2  = (const float*)d_in[4];
    float* out = (float*)d_out;

    mlp_kernel<<<376, 256>>>(ape, W1, b1, W2, b2);
    pair_kernel<<<9176, 256>>>(out);
}

// round 5
// speedup vs baseline: 1.2869x; 1.2869x over previous
#include <cuda_runtime.h>

#define N_TOT 6016

// Static shape tables: sizes g = 256 + 16*g, g in [0,16)
__constant__ int c_node_start[17] = {
    0,256,528,816,1120,1440,1776,2128,2496,2880,3280,3696,4128,4576,5040,5520,6016};
__constant__ long long c_pair_start[17] = {
    0,65536,139520,222464,314880,417280,530176,654080,789504,936960,
    1096960,1270016,1456640,1657344,1872640,2103040,2349056};
__constant__ int c_tile_start[17] = {
    0,256,545,869,1230,1630,2071,2555,3084,3660,4285,4961,5690,6474,7315,8215,9176};

// staged per-node MLP output t[N_TOT][32]
__device__ float g_t[N_TOT * 32];

// ---------------------------------------------------------------------------
// Kernel 1: per-node MLP  t = relu(ape @ W1 + b1) @ W2 + b2
// 16 threads per node, two stages, all smem accesses conflict-free:
//   Stage A: thread p computes hidden h in [4p,4p+4) via float4 sW1 reads
//            (16 lanes span 64 consecutive floats -> no conflicts)
//   Stage B: thread p computes outputs {2p,2p+1} via float2 sW2 reads
//            (16 lanes span 32 consecutive floats -> no conflicts)
// Weights kept in original row-major layout (coalesced fills, no transposes).
// 376 blocks x 16 nodes = 6016 nodes exactly.
// ---------------------------------------------------------------------------
__global__ __launch_bounds__(256)
void mlp_kernel(const float* __restrict__ ape,
                const float* __restrict__ W1, const float* __restrict__ b1,
                const float* __restrict__ W2, const float* __restrict__ b2) {
    __shared__ float sW1[16 * 64];    // row-major, as in global
    __shared__ float sW2[64 * 32];    // row-major, as in global
    __shared__ float sb1[64];
    __shared__ float sb2[32];
    __shared__ float s_in[16 * 16];   // input rows for this block's 16 nodes
    __shared__ float s_h[16 * 64];    // hidden activations per node

    int tid = threadIdx.x;
    for (int k = tid; k < 16 * 64; k += 256) sW1[k] = W1[k];
    for (int k = tid; k < 64 * 32; k += 256) sW2[k] = W2[k];
    if (tid < 64) sb1[tid] = b1[tid];
    if (tid < 32) sb2[tid] = b2[tid];
    if (tid < 64) {
        // 16 nodes x 16 floats = 64 float4, coalesced
        ((float4*)s_in)[tid] = ((const float4*)ape)[blockIdx.x * 64 + tid];
    }
    __syncthreads();

    int nl = tid >> 4;                 // node within block, 0..15
    int p  = tid & 15;
    int n  = blockIdx.x * 16 + nl;

    // Stage A: hidden values 4p..4p+3
    float v0 = sb1[4 * p + 0], v1 = sb1[4 * p + 1];
    float v2 = sb1[4 * p + 2], v3 = sb1[4 * p + 3];
    {
        const float4* w1v = (const float4*)sW1;   // w1v[k*16+p] = W1[k][4p..4p+3]
        const float*  ain = s_in + nl * 16;
#pragma unroll
        for (int k = 0; k < 16; k++) {
            float  av = ain[k];                   // broadcast (2 addrs/warp)
            float4 w  = w1v[k * 16 + p];          // conflict-free
            v0 = fmaf(av, w.x, v0);
            v1 = fmaf(av, w.y, v1);
            v2 = fmaf(av, w.z, v2);
            v3 = fmaf(av, w.w, v3);
        }
    }
    float4 hv;
    hv.x = fmaxf(v0, 0.0f); hv.y = fmaxf(v1, 0.0f);
    hv.z = fmaxf(v2, 0.0f); hv.w = fmaxf(v3, 0.0f);
    ((float4*)s_h)[nl * 16 + p] = hv;             // conflict-free
    __syncthreads();

    // Stage B: outputs 2p, 2p+1 over all 64 hidden
    float o0 = sb2[2 * p + 0], o1 = sb2[2 * p + 1];
    {
        const float4* h4p = (const float4*)(s_h + nl * 64);
        const float2* w2v = (const float2*)sW2;   // w2v[h*16+p] = W2[h][2p..2p+1]
#pragma unroll
        for (int q = 0; q < 16; q++) {
            float4 h4 = h4p[q];                   // broadcast (2 addrs/warp)
            float2 wa = w2v[(q * 4 + 0) * 16 + p];
            float2 wb = w2v[(q * 4 + 1) * 16 + p];
            float2 wc = w2v[(q * 4 + 2) * 16 + p];
            float2 wd = w2v[(q * 4 + 3) * 16 + p];
            o0 = fmaf(h4.x, wa.x, o0); o1 = fmaf(h4.x, wa.y, o1);
            o0 = fmaf(h4.y, wb.x, o0); o1 = fmaf(h4.y, wb.y, o1);
            o0 = fmaf(h4.z, wc.x, o0); o1 = fmaf(h4.z, wc.y, o1);
            o0 = fmaf(h4.w, wd.x, o0); o1 = fmaf(h4.w, wd.y, o1);
        }
    }
    float2 r2; r2.x = o0; r2.y = o1;
    *(float2*)(g_t + n * 32 + p * 2) = r2;
}

// ---------------------------------------------------------------------------
// Kernel 2: pair expansion. One block per 16x16 (i,j) tile of one graph.
// out[pair_start[b] + i*n_b + j][:] = t[start_b+i][:] + t[start_b+j][:]
// All n_b are multiples of 16 -> all tiles full, no bounds checks.
// (R1 form: 32 regs, occ ~92%, pinned at HBM write roofline.)
// ---------------------------------------------------------------------------
__global__ __launch_bounds__(256)
void pair_kernel(float* __restrict__ out) {
    int blk = blockIdx.x;

    // find graph b (uniform across block; 15 predicated compares)
    int b = 0;
#pragma unroll
    for (int g = 1; g < 16; g++)
        if (blk >= c_tile_start[g]) b = g;

    int lt  = blk - c_tile_start[b];
    int tpr = 16 + b;            // tiles per row = n_b/16
    int nb  = tpr << 4;          // n_b
    int ti  = lt / tpr;
    int tj  = lt - ti * tpr;
    int ns  = c_node_start[b];
    long long ps = c_pair_start[b];

    __shared__ float4 s_ti[16 * 8];   // 16 i-rows x 8 float4
    __shared__ float4 s_tj[16 * 8];   // 16 j-rows x 8 float4

    const float4* tp = (const float4*)g_t;
    int tid = threadIdx.x;
    if (tid < 128) {
        s_ti[tid] = tp[(ns + ti * 16) * 8 + tid];
    } else {
        s_tj[tid - 128] = tp[(ns + tj * 16) * 8 + (tid - 128)];
    }
    __syncthreads();

    float4* op = (float4*)out;
    int l    = tid & 127;        // position within a 16-row (j) group: j*8+q
    int half = tid >> 7;         // 0 or 1: which ii this thread covers per step
    int q    = l & 7;

    float4 vj = s_tj[l];         // t[j-row], float4 q — reused for all 8 steps

    long long rowbase = ps + (long long)(ti * 16) * nb + tj * 16;

#pragma unroll
    for (int step = 0; step < 8; step++) {
        int ii = step * 2 + half;
        float4 vi = s_ti[ii * 8 + q];
        float4 v;
        v.x = vi.x + vj.x; v.y = vi.y + vj.y;
        v.z = vi.z + vj.z; v.w = vi.w + vj.w;
        // 128 threads write 128 consecutive float4 (2KB contiguous)
        op[(rowbase + (long long)ii * nb) * 8 + l] = v;
    }
}

// ---------------------------------------------------------------------------
extern "C" void kernel_launch(void* const* d_in, const int* in_sizes, int n_in,
                              void* d_out, int out_size) {
    const float* ape = (const float*)d_in[0];
    const float* W1  = (const float*)d_in[1];
    const float* b1  = (const float*)d_in[2];
    const float* W2  = (const float*)d_in[3];
    const float* b2  = (const float*)d_in[4];
    float* out = (float*)d_out;

    mlp_kernel<<<376, 256>>>(ape, W1, b1, W2, b2);
    pair_kernel<<<9176, 256>>>(out);
}